// round 11
// baseline (speedup 1.0000x reference)
#include <cuda_runtime.h>
#include <cuda_fp16.h>
#include <math.h>

#define BATCH 16
#define CH    3
#define H     512
#define W     512
#define HW    (H * W)
#define KRAD  5
#define EPS_PSNR 1e-8f

#define NSEG  64
#define SEG   (H / NSEG)            // 8 owned rows per pass-2 block
#define P2_BLOCKS (BATCH * NSEG)    // 1024

__device__ __half g_sxx[BATCH * HW];   // fp16 intermediates: 3 x 8.4 MB
__device__ __half g_syy[BATCH * HW];
__device__ __half g_sxy[BATCH * HW];
__device__ float g_mse[BATCH];      // zero at module load; finalize re-zeros
__device__ float g_cos_sum;
__device__ unsigned int g_count;

// ---- L2 eviction-priority via createpolicy + cache_hint (any width) --------
__device__ __forceinline__ unsigned long long policy_evict_first() {
    unsigned long long pol;
    asm("createpolicy.fractional.L2::evict_first.b64 %0, 1.0;" : "=l"(pol));
    return pol;
}
__device__ __forceinline__ unsigned long long policy_evict_last() {
    unsigned long long pol;
    asm("createpolicy.fractional.L2::evict_last.b64 %0, 1.0;" : "=l"(pol));
    return pol;
}
__device__ __forceinline__ float4 ldg_ef(const float4* p, unsigned long long pol) {
    float4 v;
    asm("ld.global.nc.L2::cache_hint.v4.f32 {%0,%1,%2,%3}, [%4], %5;"
        : "=f"(v.x), "=f"(v.y), "=f"(v.z), "=f"(v.w) : "l"(p), "l"(pol));
    return v;
}
__device__ __forceinline__ void stg_el(void* p, uint2 v, unsigned long long pol) {
    asm volatile("st.global.L2::cache_hint.v2.u32 [%0], {%1,%2}, %3;"
                 :: "l"(p), "r"(v.x), "r"(v.y), "l"(pol) : "memory");
}

// ---------------------------------------------------------------------------
// Pass 1: one image row per block. Products + MSE + horizontal 11-tap.
// grid = BATCH*H = 8192, block = 128 (each thread 4 columns via float4)
// Inputs: evict_first (single-use 100 MB stream). Intermediates: evict_last
// (pin the 25 MB hot set in L2 for pass 2).
// ---------------------------------------------------------------------------
__global__ void __launch_bounds__(128) k_pass1(const float* __restrict__ pred,
                                               const float* __restrict__ tgt) {
    int row = blockIdx.x;
    int b = row >> 9;
    int y = row & (H - 1);
    int tid = threadIdx.x;
    int x4 = tid << 2;

    const float* pr = pred + (size_t)b * CH * HW + (size_t)y * W;
    const float* tr = tgt  + (size_t)b * CH * HW + (size_t)y * W;

    unsigned long long pef = policy_evict_first();
    unsigned long long pel = policy_evict_last();

    float4 P0 = ldg_ef((const float4*)(pr + x4), pef);
    float4 P1 = ldg_ef((const float4*)(pr + HW + x4), pef);
    float4 P2 = ldg_ef((const float4*)(pr + 2 * HW + x4), pef);
    float4 T0 = ldg_ef((const float4*)(tr + x4), pef);
    float4 T1 = ldg_ef((const float4*)(tr + HW + x4), pef);
    float4 T2 = ldg_ef((const float4*)(tr + 2 * HW + x4), pef);

    float xx0 = P0.x*P0.x + P1.x*P1.x + P2.x*P2.x;
    float xx1 = P0.y*P0.y + P1.y*P1.y + P2.y*P2.y;
    float xx2 = P0.z*P0.z + P1.z*P1.z + P2.z*P2.z;
    float xx3 = P0.w*P0.w + P1.w*P1.w + P2.w*P2.w;

    float yy0 = T0.x*T0.x + T1.x*T1.x + T2.x*T2.x;
    float yy1 = T0.y*T0.y + T1.y*T1.y + T2.y*T2.y;
    float yy2 = T0.z*T0.z + T1.z*T1.z + T2.z*T2.z;
    float yy3 = T0.w*T0.w + T1.w*T1.w + T2.w*T2.w;

    float xy0 = P0.x*T0.x + P1.x*T1.x + P2.x*T2.x;
    float xy1 = P0.y*T0.y + P1.y*T1.y + P2.y*T2.y;
    float xy2 = P0.z*T0.z + P1.z*T1.z + P2.z*T2.z;
    float xy3 = P0.w*T0.w + P1.w*T1.w + P2.w*T2.w;

    float d, msev = 0.f;
    d = P0.x - T0.x; msev += d * d;  d = P0.y - T0.y; msev += d * d;
    d = P0.z - T0.z; msev += d * d;  d = P0.w - T0.w; msev += d * d;
    d = P1.x - T1.x; msev += d * d;  d = P1.y - T1.y; msev += d * d;
    d = P1.z - T1.z; msev += d * d;  d = P1.w - T1.w; msev += d * d;
    d = P2.x - T2.x; msev += d * d;  d = P2.y - T2.y; msev += d * d;
    d = P2.z - T2.z; msev += d * d;  d = P2.w - T2.w; msev += d * d;

    __shared__ float sbuf[3][8 + W + 12];
    __shared__ float sred[4];

    float* a0 = &sbuf[0][8];
    float* a1 = &sbuf[1][8];
    float* a2 = &sbuf[2][8];

    if (tid < 8) { sbuf[0][tid] = 0.f; sbuf[1][tid] = 0.f; sbuf[2][tid] = 0.f; }
    if (tid < 12) {
        sbuf[0][8 + W + tid] = 0.f;
        sbuf[1][8 + W + tid] = 0.f;
        sbuf[2][8 + W + tid] = 0.f;
    }
    *(float4*)(a0 + x4) = make_float4(xx0, xx1, xx2, xx3);
    *(float4*)(a1 + x4) = make_float4(yy0, yy1, yy2, yy3);
    *(float4*)(a2 + x4) = make_float4(xy0, xy1, xy2, xy3);
    __syncthreads();

    size_t o = (size_t)b * HW + (size_t)y * W + x4;

    // horizontal 11-tap windows -> fp16 -> evict_last store (8B per array)
#define HWIN(a, dst)                                                         \
    {                                                                        \
        float4 q0 = *(const float4*)((a) + x4 - 8);                          \
        float4 q1 = *(const float4*)((a) + x4 - 4);                          \
        float4 q2 = *(const float4*)((a) + x4);                              \
        float4 q3 = *(const float4*)((a) + x4 + 4);                          \
        float4 q4 = *(const float4*)((a) + x4 + 8);                          \
        float w0 = q0.w + q1.x + q1.y + q1.z + q1.w                          \
                 + q2.x + q2.y + q2.z + q2.w + q3.x + q3.y;                  \
        float w1 = w0 + q3.z - q0.w;                                         \
        float w2 = w1 + q3.w - q1.x;                                         \
        float w3 = w2 + q4.x - q1.y;                                         \
        __half2 h01 = __floats2half2_rn(w0, w1);                             \
        __half2 h23 = __floats2half2_rn(w2, w3);                             \
        uint2 pk;                                                            \
        pk.x = *(const unsigned int*)&h01;                                   \
        pk.y = *(const unsigned int*)&h23;                                   \
        stg_el((dst) + o, pk, pel);                                          \
    }

    HWIN(a0, g_sxx)
    HWIN(a1, g_syy)
    HWIN(a2, g_sxy)
#undef HWIN

    int lane = tid & 31, wid = tid >> 5;
#pragma unroll
    for (int s = 16; s > 0; s >>= 1)
        msev += __shfl_xor_sync(0xffffffffu, msev, s);
    if (lane == 0) sred[wid] = msev;
    __syncthreads();
    if (tid == 0)
        atomicAdd(&g_mse[b], sred[0] + sred[1] + sred[2] + sred[3]);
}

// ---------------------------------------------------------------------------
// Pass 2: vertical 11-tap running sum + cosine (rsqrt form) + reduce.
// grid = BATCH*NSEG = 1024, block = 256 (each thread one half2 column pair)
// ---------------------------------------------------------------------------
__global__ void __launch_bounds__(256) k_pass2(float* __restrict__ out) {
    int blk = blockIdx.x;
    int seg = blk & (NSEG - 1);
    int b   = blk >> 6;
    int y0  = seg * SEG;
    int tid = threadIdx.x;

    const __half2* __restrict__ pxx = (const __half2*)g_sxx + (size_t)b * (HW / 2) + tid;
    const __half2* __restrict__ pyy = (const __half2*)g_syy + (size_t)b * (HW / 2) + tid;
    const __half2* __restrict__ pxy = (const __half2*)g_sxy + (size_t)b * (HW / 2) + tid;

    float axx0 = 0.f, axx1 = 0.f, ayy0 = 0.f, ayy1 = 0.f, axy0 = 0.f, axy1 = 0.f;

    // warm-up rows [max(0,y0-5), y0+4]  (y0+4 <= 508 < H always)
    {
        int ylo = y0 - KRAD; if (ylo < 0) ylo = 0;
        for (int y = ylo; y < y0 + KRAD; y++) {
            int r = y * (W / 2);
            float2 v;
            v = __half22float2(__ldg(pxx + r)); axx0 += v.x; axx1 += v.y;
            v = __half22float2(__ldg(pyy + r)); ayy0 += v.x; ayy1 += v.y;
            v = __half22float2(__ldg(pxy + r)); axy0 += v.x; axy1 += v.y;
        }
    }

    float csum = 0.f;
#pragma unroll
    for (int i = 0; i < SEG; i++) {
        int yy = y0 + i;
        int ya = yy + KRAD;
        if (ya < H) {
            int r = ya * (W / 2);
            float2 v;
            v = __half22float2(__ldg(pxx + r)); axx0 += v.x; axx1 += v.y;
            v = __half22float2(__ldg(pyy + r)); ayy0 += v.x; ayy1 += v.y;
            v = __half22float2(__ldg(pxy + r)); axy0 += v.x; axy1 += v.y;
        }
        // cos = axy / (sqrt(axx)*sqrt(ayy) + 1e-6)  ~=  axy * rsqrt(axx*ayy)
        csum += axy0 * rsqrtf(axx0 * ayy0);
        csum += axy1 * rsqrtf(axx1 * ayy1);
        int yr = yy - KRAD;
        if (yr >= 0) {
            int r = yr * (W / 2);
            float2 v;
            v = __half22float2(__ldg(pxx + r)); axx0 -= v.x; axx1 -= v.y;
            v = __half22float2(__ldg(pyy + r)); ayy0 -= v.x; ayy1 -= v.y;
            v = __half22float2(__ldg(pxy + r)); axy0 -= v.x; axy1 -= v.y;
        }
    }

    // block reduce csum
    __shared__ float sred[8];
    int lane = tid & 31, wid = tid >> 5;
#pragma unroll
    for (int s = 16; s > 0; s >>= 1)
        csum += __shfl_xor_sync(0xffffffffu, csum, s);
    if (lane == 0) sred[wid] = csum;
    __syncthreads();
    if (tid == 0) {
        float t = sred[0] + sred[1] + sred[2] + sred[3]
                + sred[4] + sred[5] + sred[6] + sred[7];
        atomicAdd(&g_cos_sum, t);
    }

    // last-block fused finalize
    __shared__ unsigned int amLast;
    if (tid == 0) {
        __threadfence();
        amLast = (atomicAdd(&g_count, 1u) == (unsigned)(P2_BLOCKS - 1));
    }
    __syncthreads();
    if (amLast && tid < 32) {
        float v = 0.f;
        if (tid < BATCH)
            v = logf(g_mse[tid] * (1.0f / (float)(CH * HW)) + EPS_PSNR);
#pragma unroll
        for (int s = 16; s > 0; s >>= 1)
            v += __shfl_xor_sync(0xffffffffu, v, s);
        if (tid == 0) {
            const float scale = 10.0f / logf(10.0f);
            float psnr_loss = scale * (v * (1.0f / (float)BATCH));
            float lcs_loss  = 1.0f - g_cos_sum * (1.0f / (float)(BATCH * HW));
            out[0] = psnr_loss + lcs_loss;
            g_cos_sum = 0.0f;
            g_count = 0u;
        }
        if (tid < BATCH) g_mse[tid] = 0.0f;
    }
}

// ---------------------------------------------------------------------------
extern "C" void kernel_launch(void* const* d_in, const int* in_sizes, int n_in,
                              void* d_out, int out_size) {
    const float* pred = (const float*)d_in[0];
    const float* tgt  = (const float*)d_in[1];
    float* out = (float*)d_out;

    k_pass1<<<BATCH * H, 128>>>(pred, tgt);
    k_pass2<<<P2_BLOCKS, 256>>>(out);
}

// round 14
// speedup vs baseline: 1.1781x; 1.1781x over previous
#include <cuda_runtime.h>
#include <cuda_fp16.h>
#include <math.h>

#define BATCH 16
#define CH    3
#define H     512
#define W     512
#define HW    (H * W)
#define KRAD  5
#define EPS_PSNR 1e-8f

#define NSEG  64
#define SEG   (H / NSEG)                    // 8 owned rows per pass-2 block
#define XSPL  2
#define P2_BLOCKS (BATCH * NSEG * XSPL)     // 2048

// Packed fp16 intermediates: g_ab[pixel] = half2(xx, yy); g_xy[pixel] = xy
__device__ unsigned int g_ab[BATCH * HW];   // 16.8 MB
__device__ __half       g_xy[BATCH * HW];   //  8.4 MB
__device__ float g_mse[BATCH];      // zero at module load; finalize re-zeros
__device__ float g_cos_sum;
__device__ unsigned int g_count;

// ---------------------------------------------------------------------------
// Pass 1: one image row per block. Products + MSE + horizontal 11-tap.
// grid = BATCH*H = 8192, block = 128 (each thread 4 columns via float4)
// ---------------------------------------------------------------------------
__global__ void __launch_bounds__(128) k_pass1(const float* __restrict__ pred,
                                               const float* __restrict__ tgt) {
    int row = blockIdx.x;
    int b = row >> 9;
    int y = row & (H - 1);
    int tid = threadIdx.x;
    int x4 = tid << 2;

    const float* pr = pred + (size_t)b * CH * HW + (size_t)y * W;
    const float* tr = tgt  + (size_t)b * CH * HW + (size_t)y * W;

    float4 P0 = __ldcs((const float4*)(pr + x4));
    float4 P1 = __ldcs((const float4*)(pr + HW + x4));
    float4 P2 = __ldcs((const float4*)(pr + 2 * HW + x4));
    float4 T0 = __ldcs((const float4*)(tr + x4));
    float4 T1 = __ldcs((const float4*)(tr + HW + x4));
    float4 T2 = __ldcs((const float4*)(tr + 2 * HW + x4));

    float xx0 = P0.x*P0.x + P1.x*P1.x + P2.x*P2.x;
    float xx1 = P0.y*P0.y + P1.y*P1.y + P2.y*P2.y;
    float xx2 = P0.z*P0.z + P1.z*P1.z + P2.z*P2.z;
    float xx3 = P0.w*P0.w + P1.w*P1.w + P2.w*P2.w;

    float yy0 = T0.x*T0.x + T1.x*T1.x + T2.x*T2.x;
    float yy1 = T0.y*T0.y + T1.y*T1.y + T2.y*T2.y;
    float yy2 = T0.z*T0.z + T1.z*T1.z + T2.z*T2.z;
    float yy3 = T0.w*T0.w + T1.w*T1.w + T2.w*T2.w;

    float xy0 = P0.x*T0.x + P1.x*T1.x + P2.x*T2.x;
    float xy1 = P0.y*T0.y + P1.y*T1.y + P2.y*T2.y;
    float xy2 = P0.z*T0.z + P1.z*T1.z + P2.z*T2.z;
    float xy3 = P0.w*T0.w + P1.w*T1.w + P2.w*T2.w;

    float d, msev = 0.f;
    d = P0.x - T0.x; msev += d * d;  d = P0.y - T0.y; msev += d * d;
    d = P0.z - T0.z; msev += d * d;  d = P0.w - T0.w; msev += d * d;
    d = P1.x - T1.x; msev += d * d;  d = P1.y - T1.y; msev += d * d;
    d = P1.z - T1.z; msev += d * d;  d = P1.w - T1.w; msev += d * d;
    d = P2.x - T2.x; msev += d * d;  d = P2.y - T2.y; msev += d * d;
    d = P2.z - T2.z; msev += d * d;  d = P2.w - T2.w; msev += d * d;

    __shared__ float sbuf[3][8 + W + 12];
    __shared__ float sred[4];

    float* a0 = &sbuf[0][8];
    float* a1 = &sbuf[1][8];
    float* a2 = &sbuf[2][8];

    if (tid < 8) { sbuf[0][tid] = 0.f; sbuf[1][tid] = 0.f; sbuf[2][tid] = 0.f; }
    if (tid < 12) {
        sbuf[0][8 + W + tid] = 0.f;
        sbuf[1][8 + W + tid] = 0.f;
        sbuf[2][8 + W + tid] = 0.f;
    }
    *(float4*)(a0 + x4) = make_float4(xx0, xx1, xx2, xx3);
    *(float4*)(a1 + x4) = make_float4(yy0, yy1, yy2, yy3);
    *(float4*)(a2 + x4) = make_float4(xy0, xy1, xy2, xy3);
    __syncthreads();

    size_t o = (size_t)b * HW + (size_t)y * W + x4;

    // horizontal 11-tap windows into dst_[0..3]
#define HWIN(a, dst_)                                                        \
    {                                                                        \
        float4 q0 = *(const float4*)((a) + x4 - 8);                          \
        float4 q1 = *(const float4*)((a) + x4 - 4);                          \
        float4 q2 = *(const float4*)((a) + x4);                              \
        float4 q3 = *(const float4*)((a) + x4 + 4);                          \
        float4 q4 = *(const float4*)((a) + x4 + 8);                          \
        dst_[0] = q0.w + q1.x + q1.y + q1.z + q1.w                           \
                + q2.x + q2.y + q2.z + q2.w + q3.x + q3.y;                   \
        dst_[1] = dst_[0] + q3.z - q0.w;                                     \
        dst_[2] = dst_[1] + q3.w - q1.x;                                     \
        dst_[3] = dst_[2] + q4.x - q1.y;                                     \
    }

    float hxx[4], hyy[4], hxy[4];
    HWIN(a0, hxx)
    HWIN(a1, hyy)
    HWIN(a2, hxy)
#undef HWIN

    // pack: g_ab[o+i] = half2(xx_i, yy_i); g_xy[o+i] = half(xy_i)
    __half2 ab0 = __floats2half2_rn(hxx[0], hyy[0]);
    __half2 ab1 = __floats2half2_rn(hxx[1], hyy[1]);
    __half2 ab2 = __floats2half2_rn(hxx[2], hyy[2]);
    __half2 ab3 = __floats2half2_rn(hxx[3], hyy[3]);
    uint4 pa;
    pa.x = *(const unsigned int*)&ab0;
    pa.y = *(const unsigned int*)&ab1;
    pa.z = *(const unsigned int*)&ab2;
    pa.w = *(const unsigned int*)&ab3;
    *(uint4*)(g_ab + o) = pa;

    __half2 xy01 = __floats2half2_rn(hxy[0], hxy[1]);
    __half2 xy23 = __floats2half2_rn(hxy[2], hxy[3]);
    uint2 pb;
    pb.x = *(const unsigned int*)&xy01;
    pb.y = *(const unsigned int*)&xy23;
    *(uint2*)(g_xy + o) = pb;

    int lane = tid & 31, wid = tid >> 5;
#pragma unroll
    for (int s = 16; s > 0; s >>= 1)
        msev += __shfl_xor_sync(0xffffffffu, msev, s);
    if (lane == 0) sred[wid] = msev;
    __syncthreads();
    if (tid == 0)
        atomicAdd(&g_mse[b], sred[0] + sred[1] + sred[2] + sred[3]);
}

// ---------------------------------------------------------------------------
// Pass 2: vertical 11-tap running sum + cosine (rsqrt form) + reduce.
// grid = 2048 (16 batch x 64 segs x 2 strips), block = 128, 2 px/thread
// Per iteration: 2 loads per stream (8B ab + 4B xy), add + sub = 4 loads.
// ---------------------------------------------------------------------------
__global__ void __launch_bounds__(128) k_pass2(float* __restrict__ out) {
    int blk = blockIdx.x;
    int xs  = blk & (XSPL - 1);  blk >>= 1;
    int seg = blk & (NSEG - 1);
    int b   = blk >> 6;
    int y0  = seg * SEG;
    int tid = threadIdx.x;
    int x2  = (xs << 7) + tid;          // pixel-pair index within row [0,256)

    const uint2*   __restrict__ pab = (const uint2*)g_ab + (size_t)b * (HW / 2) + x2;
    const __half2* __restrict__ pxy = (const __half2*)g_xy + (size_t)b * (HW / 2) + x2;

    float axx0 = 0.f, axx1 = 0.f, ayy0 = 0.f, ayy1 = 0.f, axy0 = 0.f, axy1 = 0.f;

#define ACC_ADD(r)                                                           \
    {                                                                        \
        uint2 va = __ldg(pab + (r));                                         \
        __half2 hb = __ldg(pxy + (r));                                       \
        float2 f0 = __half22float2(*(const __half2*)&va.x);                  \
        float2 f1 = __half22float2(*(const __half2*)&va.y);                  \
        float2 fb = __half22float2(hb);                                      \
        axx0 += f0.x; ayy0 += f0.y;                                          \
        axx1 += f1.x; ayy1 += f1.y;                                          \
        axy0 += fb.x; axy1 += fb.y;                                          \
    }
#define ACC_SUB(r)                                                           \
    {                                                                        \
        uint2 va = __ldg(pab + (r));                                         \
        __half2 hb = __ldg(pxy + (r));                                       \
        float2 f0 = __half22float2(*(const __half2*)&va.x);                  \
        float2 f1 = __half22float2(*(const __half2*)&va.y);                  \
        float2 fb = __half22float2(hb);                                      \
        axx0 -= f0.x; ayy0 -= f0.y;                                          \
        axx1 -= f1.x; ayy1 -= f1.y;                                          \
        axy0 -= fb.x; axy1 -= fb.y;                                          \
    }

    // warm-up rows [max(0,y0-5), y0+4]  (y0+4 <= 508 < H always)
    {
        int ylo = y0 - KRAD; if (ylo < 0) ylo = 0;
        for (int y = ylo; y < y0 + KRAD; y++)
            ACC_ADD(y * (W / 2))
    }

    float csum = 0.f;
#pragma unroll
    for (int i = 0; i < SEG; i++) {
        int yy = y0 + i;
        int ya = yy + KRAD;
        if (ya < H)
            ACC_ADD(ya * (W / 2))
        // cos = axy / (sqrt(axx)*sqrt(ayy) + 1e-6)  ~=  axy * rsqrt(axx*ayy)
        csum += axy0 * rsqrtf(axx0 * ayy0);
        csum += axy1 * rsqrtf(axx1 * ayy1);
        int yr = yy - KRAD;
        if (yr >= 0)
            ACC_SUB(yr * (W / 2))
    }
#undef ACC_ADD
#undef ACC_SUB

    // block reduce csum (4 warps)
    __shared__ float sred[4];
    int lane = tid & 31, wid = tid >> 5;
#pragma unroll
    for (int s = 16; s > 0; s >>= 1)
        csum += __shfl_xor_sync(0xffffffffu, csum, s);
    if (lane == 0) sred[wid] = csum;
    __syncthreads();
    if (tid == 0)
        atomicAdd(&g_cos_sum, sred[0] + sred[1] + sred[2] + sred[3]);

    // last-block fused finalize
    __shared__ unsigned int amLast;
    if (tid == 0) {
        __threadfence();
        amLast = (atomicAdd(&g_count, 1u) == (unsigned)(P2_BLOCKS - 1));
    }
    __syncthreads();
    if (amLast && tid < 32) {
        float v = 0.f;
        if (tid < BATCH)
            v = logf(g_mse[tid] * (1.0f / (float)(CH * HW)) + EPS_PSNR);
#pragma unroll
        for (int s = 16; s > 0; s >>= 1)
            v += __shfl_xor_sync(0xffffffffu, v, s);
        if (tid == 0) {
            const float scale = 10.0f / logf(10.0f);
            float psnr_loss = scale * (v * (1.0f / (float)BATCH));
            float lcs_loss  = 1.0f - g_cos_sum * (1.0f / (float)(BATCH * HW));
            out[0] = psnr_loss + lcs_loss;
            g_cos_sum = 0.0f;
            g_count = 0u;
        }
        if (tid < BATCH) g_mse[tid] = 0.0f;
    }
}

// ---------------------------------------------------------------------------
extern "C" void kernel_launch(void* const* d_in, const int* in_sizes, int n_in,
                              void* d_out, int out_size) {
    const float* pred = (const float*)d_in[0];
    const float* tgt  = (const float*)d_in[1];
    float* out = (float*)d_out;

    k_pass1<<<BATCH * H, 128>>>(pred, tgt);
    k_pass2<<<P2_BLOCKS, 128>>>(out);
}

// round 15
// speedup vs baseline: 1.1873x; 1.0078x over previous
#include <cuda_runtime.h>
#include <cuda_fp16.h>
#include <math.h>

#define BATCH 16
#define CH    3
#define H     512
#define W     512
#define HW    (H * W)
#define KRAD  5
#define EPS_PSNR 1e-8f

#define NSEG  64
#define SEG   (H / NSEG)                    // 8 owned rows per pass-2 block
#define XSPL  2
#define P2_BLOCKS (BATCH * NSEG * XSPL)     // 2048

// Packed fp16 intermediates: g_ab[pixel] = half2(xx, yy); g_xy[pixel] = xy
__device__ unsigned int g_ab[BATCH * HW];   // 16.8 MB
__device__ __half       g_xy[BATCH * HW];   //  8.4 MB
__device__ float g_mse[BATCH];      // zero at module load; finalize re-zeros
__device__ float g_cos_sum;
__device__ unsigned int g_count;

// ---------------------------------------------------------------------------
// Pass 1: one image row per block. Products + MSE + horizontal 11-tap.
// grid = BATCH*H = 8192, block = 128 (each thread 4 columns via float4)
// ---------------------------------------------------------------------------
__global__ void __launch_bounds__(128) k_pass1(const float* __restrict__ pred,
                                               const float* __restrict__ tgt) {
    int row = blockIdx.x;
    int b = row >> 9;
    int y = row & (H - 1);
    int tid = threadIdx.x;
    int x4 = tid << 2;

    const float* pr = pred + (size_t)b * CH * HW + (size_t)y * W;
    const float* tr = tgt  + (size_t)b * CH * HW + (size_t)y * W;

    float4 P0 = __ldcs((const float4*)(pr + x4));
    float4 P1 = __ldcs((const float4*)(pr + HW + x4));
    float4 P2 = __ldcs((const float4*)(pr + 2 * HW + x4));
    float4 T0 = __ldcs((const float4*)(tr + x4));
    float4 T1 = __ldcs((const float4*)(tr + HW + x4));
    float4 T2 = __ldcs((const float4*)(tr + 2 * HW + x4));

    float xx0 = P0.x*P0.x + P1.x*P1.x + P2.x*P2.x;
    float xx1 = P0.y*P0.y + P1.y*P1.y + P2.y*P2.y;
    float xx2 = P0.z*P0.z + P1.z*P1.z + P2.z*P2.z;
    float xx3 = P0.w*P0.w + P1.w*P1.w + P2.w*P2.w;

    float yy0 = T0.x*T0.x + T1.x*T1.x + T2.x*T2.x;
    float yy1 = T0.y*T0.y + T1.y*T1.y + T2.y*T2.y;
    float yy2 = T0.z*T0.z + T1.z*T1.z + T2.z*T2.z;
    float yy3 = T0.w*T0.w + T1.w*T1.w + T2.w*T2.w;

    float xy0 = P0.x*T0.x + P1.x*T1.x + P2.x*T2.x;
    float xy1 = P0.y*T0.y + P1.y*T1.y + P2.y*T2.y;
    float xy2 = P0.z*T0.z + P1.z*T1.z + P2.z*T2.z;
    float xy3 = P0.w*T0.w + P1.w*T1.w + P2.w*T2.w;

    float d, msev = 0.f;
    d = P0.x - T0.x; msev += d * d;  d = P0.y - T0.y; msev += d * d;
    d = P0.z - T0.z; msev += d * d;  d = P0.w - T0.w; msev += d * d;
    d = P1.x - T1.x; msev += d * d;  d = P1.y - T1.y; msev += d * d;
    d = P1.z - T1.z; msev += d * d;  d = P1.w - T1.w; msev += d * d;
    d = P2.x - T2.x; msev += d * d;  d = P2.y - T2.y; msev += d * d;
    d = P2.z - T2.z; msev += d * d;  d = P2.w - T2.w; msev += d * d;

    __shared__ float sbuf[3][8 + W + 12];
    __shared__ float sred[4];

    float* a0 = &sbuf[0][8];
    float* a1 = &sbuf[1][8];
    float* a2 = &sbuf[2][8];

    if (tid < 8) { sbuf[0][tid] = 0.f; sbuf[1][tid] = 0.f; sbuf[2][tid] = 0.f; }
    if (tid < 12) {
        sbuf[0][8 + W + tid] = 0.f;
        sbuf[1][8 + W + tid] = 0.f;
        sbuf[2][8 + W + tid] = 0.f;
    }
    *(float4*)(a0 + x4) = make_float4(xx0, xx1, xx2, xx3);
    *(float4*)(a1 + x4) = make_float4(yy0, yy1, yy2, yy3);
    *(float4*)(a2 + x4) = make_float4(xy0, xy1, xy2, xy3);
    __syncthreads();

    size_t o = (size_t)b * HW + (size_t)y * W + x4;

    // horizontal 11-tap windows into dst_[0..3]
#define HWIN(a, dst_)                                                        \
    {                                                                        \
        float4 q0 = *(const float4*)((a) + x4 - 8);                          \
        float4 q1 = *(const float4*)((a) + x4 - 4);                          \
        float4 q2 = *(const float4*)((a) + x4);                              \
        float4 q3 = *(const float4*)((a) + x4 + 4);                          \
        float4 q4 = *(const float4*)((a) + x4 + 8);                          \
        dst_[0] = q0.w + q1.x + q1.y + q1.z + q1.w                           \
                + q2.x + q2.y + q2.z + q2.w + q3.x + q3.y;                   \
        dst_[1] = dst_[0] + q3.z - q0.w;                                     \
        dst_[2] = dst_[1] + q3.w - q1.x;                                     \
        dst_[3] = dst_[2] + q4.x - q1.y;                                     \
    }

    float hxx[4], hyy[4], hxy[4];
    HWIN(a0, hxx)
    HWIN(a1, hyy)
    HWIN(a2, hxy)
#undef HWIN

    // pack: g_ab[o+i] = half2(xx_i, yy_i); g_xy[o+i] = half(xy_i)
    __half2 ab0 = __floats2half2_rn(hxx[0], hyy[0]);
    __half2 ab1 = __floats2half2_rn(hxx[1], hyy[1]);
    __half2 ab2 = __floats2half2_rn(hxx[2], hyy[2]);
    __half2 ab3 = __floats2half2_rn(hxx[3], hyy[3]);
    uint4 pa;
    pa.x = *(const unsigned int*)&ab0;
    pa.y = *(const unsigned int*)&ab1;
    pa.z = *(const unsigned int*)&ab2;
    pa.w = *(const unsigned int*)&ab3;
    *(uint4*)(g_ab + o) = pa;

    __half2 xy01 = __floats2half2_rn(hxy[0], hxy[1]);
    __half2 xy23 = __floats2half2_rn(hxy[2], hxy[3]);
    uint2 pb;
    pb.x = *(const unsigned int*)&xy01;
    pb.y = *(const unsigned int*)&xy23;
    *(uint2*)(g_xy + o) = pb;

    int lane = tid & 31, wid = tid >> 5;
#pragma unroll
    for (int s = 16; s > 0; s >>= 1)
        msev += __shfl_xor_sync(0xffffffffu, msev, s);
    if (lane == 0) sred[wid] = msev;
    __syncthreads();
    if (tid == 0)
        atomicAdd(&g_mse[b], sred[0] + sred[1] + sred[2] + sred[3]);
}

// ---------------------------------------------------------------------------
// Pass 2: vertical 11-tap running sum with REGISTER ring for the subtract
// stream (SEG=8 => the 8 subtracted rows are exactly the first 8 warm-up
// rows; keep their raw values in registers, no re-load).
// grid = 2048 (16 batch x 64 segs x 2 strips), block = 128, 2 px/thread.
// Loads per thread: 10 warm-up + 8 steady = 18 (was 26).
// ---------------------------------------------------------------------------
__global__ void __launch_bounds__(128) k_pass2(float* __restrict__ out) {
    int blk = blockIdx.x;
    int xs  = blk & (XSPL - 1);  blk >>= 1;
    int seg = blk & (NSEG - 1);
    int b   = blk >> 6;
    int y0  = seg * SEG;
    int tid = threadIdx.x;
    int x2  = (xs << 7) + tid;          // pixel-pair index within row [0,256)

    const uint2*   __restrict__ pab = (const uint2*)g_ab + (size_t)b * (HW / 2) + x2;
    const __half2* __restrict__ pxy = (const __half2*)g_xy + (size_t)b * (HW / 2) + x2;

    float axx0 = 0.f, axx1 = 0.f, ayy0 = 0.f, ayy1 = 0.f, axy0 = 0.f, axy1 = 0.f;

    const __half2 hzero = __float2half2_rn(0.0f);

    // register ring: raw values of rows y0-5+i for i = 0..SEG-1
    uint2   rva[SEG];
    __half2 rhb[SEG];

    // warm-up: rows y0-5 .. y0+4, fully unrolled; save first SEG rows
#pragma unroll
    for (int j = 0; j < 2 * KRAD; j++) {
        int y = y0 - KRAD + j;
        uint2 va = make_uint2(0u, 0u);
        __half2 hb = hzero;
        if (y >= 0) {                       // y0+4 <= 508 < H always
            int r = y * (W / 2);
            va = __ldg(pab + r);
            hb = __ldg(pxy + r);
        }
        if (j < SEG) { rva[j] = va; rhb[j] = hb; }
        float2 f0 = __half22float2(*(const __half2*)&va.x);
        float2 f1 = __half22float2(*(const __half2*)&va.y);
        float2 fb = __half22float2(hb);
        axx0 += f0.x; ayy0 += f0.y;
        axx1 += f1.x; ayy1 += f1.y;
        axy0 += fb.x; axy1 += fb.y;
    }

    float csum = 0.f;
#pragma unroll
    for (int i = 0; i < SEG; i++) {
        int ya = y0 + KRAD + i;
        uint2 va = make_uint2(0u, 0u);
        __half2 hb = hzero;
        if (ya < H) {
            int r = ya * (W / 2);
            va = __ldg(pab + r);
            hb = __ldg(pxy + r);
        }
        {   // add row ya
            float2 f0 = __half22float2(*(const __half2*)&va.x);
            float2 f1 = __half22float2(*(const __half2*)&va.y);
            float2 fb = __half22float2(hb);
            axx0 += f0.x; ayy0 += f0.y;
            axx1 += f1.x; ayy1 += f1.y;
            axy0 += fb.x; axy1 += fb.y;
        }
        // cos = axy / (sqrt(axx)*sqrt(ayy) + 1e-6)  ~=  axy * rsqrt(axx*ayy)
        csum += axy0 * rsqrtf(axx0 * ayy0);
        csum += axy1 * rsqrtf(axx1 * ayy1);
        {   // subtract row y0-5+i from the register ring
            float2 f0 = __half22float2(*(const __half2*)&rva[i].x);
            float2 f1 = __half22float2(*(const __half2*)&rva[i].y);
            float2 fb = __half22float2(rhb[i]);
            axx0 -= f0.x; ayy0 -= f0.y;
            axx1 -= f1.x; ayy1 -= f1.y;
            axy0 -= fb.x; axy1 -= fb.y;
        }
    }

    // block reduce csum (4 warps)
    __shared__ float sred[4];
    int lane = tid & 31, wid = tid >> 5;
#pragma unroll
    for (int s = 16; s > 0; s >>= 1)
        csum += __shfl_xor_sync(0xffffffffu, csum, s);
    if (lane == 0) sred[wid] = csum;
    __syncthreads();
    if (tid == 0)
        atomicAdd(&g_cos_sum, sred[0] + sred[1] + sred[2] + sred[3]);

    // last-block fused finalize
    __shared__ unsigned int amLast;
    if (tid == 0) {
        __threadfence();
        amLast = (atomicAdd(&g_count, 1u) == (unsigned)(P2_BLOCKS - 1));
    }
    __syncthreads();
    if (amLast && tid < 32) {
        float v = 0.f;
        if (tid < BATCH)
            v = logf(g_mse[tid] * (1.0f / (float)(CH * HW)) + EPS_PSNR);
#pragma unroll
        for (int s = 16; s > 0; s >>= 1)
            v += __shfl_xor_sync(0xffffffffu, v, s);
        if (tid == 0) {
            const float scale = 10.0f / logf(10.0f);
            float psnr_loss = scale * (v * (1.0f / (float)BATCH));
            float lcs_loss  = 1.0f - g_cos_sum * (1.0f / (float)(BATCH * HW));
            out[0] = psnr_loss + lcs_loss;
            g_cos_sum = 0.0f;
            g_count = 0u;
        }
        if (tid < BATCH) g_mse[tid] = 0.0f;
    }
}

// ---------------------------------------------------------------------------
extern "C" void kernel_launch(void* const* d_in, const int* in_sizes, int n_in,
                              void* d_out, int out_size) {
    const float* pred = (const float*)d_in[0];
    const float* tgt  = (const float*)d_in[1];
    float* out = (float*)d_out;

    k_pass1<<<BATCH * H, 128>>>(pred, tgt);
    k_pass2<<<P2_BLOCKS, 128>>>(out);
}